// round 1
// baseline (speedup 1.0000x reference)
#include <cuda_runtime.h>
#include <math.h>

// Problem constants
#define BB 4
#define DD 1024
#define NHH 16
#define DHH 64
#define EE 32
#define LQQ 1024
#define NPP 4

// ---------------- scratch (device globals; no allocation allowed) ----------------
__device__ float g_qn   [BB * LQQ * DD];            // layer_norm(query)
__device__ float g_fn   [BB * 4 * LQQ * DD];        // layer_norm(feat)
__device__ float g_val  [BB * 4 * LQQ * DD];        // CA value
__device__ float g_off  [BB * LQQ * 512];           // CA offsets
__device__ float g_attw [BB * LQQ * 256];           // CA attention weights (logits -> softmax in place)
__device__ float g_samp [BB * LQQ * DD];            // CA sampled output
__device__ float g_attn [BB * LQQ * DD];            // CA projected output
__device__ float g_attn1[BB * LQQ * DD];            // layer_norm(attn)
__device__ float g_val2 [BB * LQQ * DD];            // SA value
__device__ float g_off2 [BB * LQQ * 128];
__device__ float g_attw2[BB * LQQ * 64];
__device__ float g_samp2[BB * LQQ * DD];
__device__ float g_attn2[BB * LQQ * DD];

// ---------------- layernorm: one block (256 thr) per row of 1024 ----------------
__global__ void __launch_bounds__(256) layernorm_kernel(
    const float* __restrict__ in, const float* __restrict__ g, const float* __restrict__ b,
    float* __restrict__ out, int rows_per_batch, int out_batch_stride_rows, int out_row_offset)
{
    int r = blockIdx.x;
    int n = r / rows_per_batch, q = r - n * rows_per_batch;
    const float* x = in + (size_t)r * DD;
    float* y = out + ((size_t)n * out_batch_stride_rows + out_row_offset + q) * DD;
    int t = threadIdx.x;

    float4 v = ((const float4*)x)[t];
    float s  = v.x + v.y + v.z + v.w;
    float ss = v.x*v.x + v.y*v.y + v.z*v.z + v.w*v.w;
    #pragma unroll
    for (int o = 16; o > 0; o >>= 1) {
        s  += __shfl_xor_sync(0xffffffffu, s,  o);
        ss += __shfl_xor_sync(0xffffffffu, ss, o);
    }
    __shared__ float sh_s[8], sh_ss[8];
    int wid = t >> 5, lane = t & 31;
    if (lane == 0) { sh_s[wid] = s; sh_ss[wid] = ss; }
    __syncthreads();
    s = 0.f; ss = 0.f;
    #pragma unroll
    for (int i = 0; i < 8; i++) { s += sh_s[i]; ss += sh_ss[i]; }
    float mean = s * (1.0f / DD);
    float var  = ss * (1.0f / DD) - mean * mean;
    float inv  = rsqrtf(var + 1e-6f);

    float4 gg = ((const float4*)g)[t];
    float4 bb2 = ((const float4*)b)[t];
    float4 o4;
    o4.x = (v.x - mean) * inv * gg.x + bb2.x;
    o4.y = (v.y - mean) * inv * gg.y + bb2.y;
    o4.z = (v.z - mean) * inv * gg.z + bb2.z;
    o4.w = (v.w - mean) * inv * gg.w + bb2.w;
    ((float4*)y)[t] = o4;
}

// ---------------- GEMM: C[M,N] = A[M,K] @ W[N,K]^T + bias ----------------
// 64x64 tile, TK=16, 256 threads, 4x4 microtile
__global__ void __launch_bounds__(256) gemm_bias_kernel(
    const float* __restrict__ A, const float* __restrict__ W,
    const float* __restrict__ bias, float* __restrict__ C,
    int M, int N, int K)
{
    __shared__ float As[16][64];
    __shared__ float Ws[16][64];
    const int tid = threadIdx.x;
    const int tx = tid & 15, ty = tid >> 4;
    const int m0 = blockIdx.y << 6, n0 = blockIdx.x << 6;

    float acc[4][4] = {};

    const int i  = tid << 2;
    const int lm = i >> 4;   // 0..63
    const int lk = i & 15;   // 0,4,8,12
    const float* Aptr = A + (size_t)(m0 + lm) * K + lk;
    const float* Wptr = W + (size_t)(n0 + lm) * K + lk;

    for (int k0 = 0; k0 < K; k0 += 16) {
        float4 av = *(const float4*)(Aptr + k0);
        float4 wv = *(const float4*)(Wptr + k0);
        As[lk + 0][lm] = av.x; As[lk + 1][lm] = av.y; As[lk + 2][lm] = av.z; As[lk + 3][lm] = av.w;
        Ws[lk + 0][lm] = wv.x; Ws[lk + 1][lm] = wv.y; Ws[lk + 2][lm] = wv.z; Ws[lk + 3][lm] = wv.w;
        __syncthreads();
        #pragma unroll
        for (int k = 0; k < 16; k++) {
            float4 a = *(const float4*)&As[k][ty << 2];
            float4 b = *(const float4*)&Ws[k][tx << 2];
            acc[0][0] += a.x * b.x; acc[0][1] += a.x * b.y; acc[0][2] += a.x * b.z; acc[0][3] += a.x * b.w;
            acc[1][0] += a.y * b.x; acc[1][1] += a.y * b.y; acc[1][2] += a.y * b.z; acc[1][3] += a.y * b.w;
            acc[2][0] += a.z * b.x; acc[2][1] += a.z * b.y; acc[2][2] += a.z * b.z; acc[2][3] += a.z * b.w;
            acc[3][0] += a.w * b.x; acc[3][1] += a.w * b.y; acc[3][2] += a.w * b.z; acc[3][3] += a.w * b.w;
        }
        __syncthreads();
    }

    float4 bv = *(const float4*)(bias + n0 + (tx << 2));
    #pragma unroll
    for (int r = 0; r < 4; r++) {
        float4 o;
        o.x = acc[r][0] + bv.x;
        o.y = acc[r][1] + bv.y;
        o.z = acc[r][2] + bv.z;
        o.w = acc[r][3] + bv.w;
        *(float4*)(C + (size_t)(m0 + (ty << 2) + r) * N + n0 + (tx << 2)) = o;
    }
}

// ---------------- softmax over P contiguous values, one thread per group ----------------
template<int P>
__global__ void softmax_kernel(float* __restrict__ w, int ngroups)
{
    int gid = blockIdx.x * blockDim.x + threadIdx.x;
    if (gid >= ngroups) return;
    float* p = w + (size_t)gid * P;
    float mx = p[0];
    #pragma unroll
    for (int i = 1; i < P; i++) mx = fmaxf(mx, p[i]);
    float s = 0.f;
    float e[P];
    #pragma unroll
    for (int i = 0; i < P; i++) { e[i] = __expf(p[i] - mx); s += e[i]; }
    float inv = 1.0f / s;
    #pragma unroll
    for (int i = 0; i < P; i++) p[i] = e[i] * inv;
}

// ---------------- deformable sampling ----------------
// grid (NH, LQ, B), block DH(=64) threads, one per dh channel
template<int NL>
__global__ void __launch_bounds__(64) sample_kernel(
    const float* __restrict__ val,   // (B, NL*LQ, D) value, per-level blocks of LQ rows
    const float* __restrict__ off,   // (B, LQ, NH*NL*NP*2)
    const float* __restrict__ attw,  // (B, LQ, NH*NL*NP) softmaxed
    float* __restrict__ out)         // (B, LQ, D)
{
    const int h  = blockIdx.x;
    const int lq = blockIdx.y;
    const int n  = blockIdx.z;
    const int dh = threadIdx.x;

    const float refx = ((lq & 31) + 0.5f) * 0.03125f;
    const float refy = ((lq >> 5) + 0.5f) * 0.03125f;

    const float* op = off  + (size_t)(n * LQQ + lq) * (NL * 128) + h * (NL * 8);
    const float* wp = attw + (size_t)(n * LQQ + lq) * (NL * 64)  + h * (NL * 4);
    const float* vb = val  + (size_t)n * (NL * LQQ) * DD + h * DHH + dh;

    float acc = 0.f;
    #pragma unroll
    for (int l = 0; l < NL; l++) {
        const float* vl = vb + (size_t)l * LQQ * DD;
        #pragma unroll
        for (int p = 0; p < NPP; p++) {
            float ox = op[l * 8 + p * 2 + 0];
            float oy = op[l * 8 + p * 2 + 1];
            float x = (refx + ox * 0.03125f) * 32.f - 0.5f;
            float y = (refy + oy * 0.03125f) * 32.f - 0.5f;
            float x0f = floorf(x), y0f = floorf(y);
            int xi = (int)x0f, yi = (int)y0f;
            float fx = x - x0f, fy = y - y0f;
            float w = wp[l * 4 + p];
            float w00 = (1.f - fy) * (1.f - fx) * w;
            float w01 = (1.f - fy) * fx * w;
            float w10 = fy * (1.f - fx) * w;
            float w11 = fy * fx * w;
            bool xv0 = (xi >= 0) && (xi < 32);
            bool xv1 = (xi + 1 >= 0) && (xi + 1 < 32);
            if (yi >= 0 && yi < 32) {
                const float* row = vl + (size_t)yi * 32 * DD;
                if (xv0) acc += w00 * row[(size_t)xi * DD];
                if (xv1) acc += w01 * row[(size_t)(xi + 1) * DD];
            }
            if (yi + 1 >= 0 && yi + 1 < 32) {
                const float* row = vl + (size_t)(yi + 1) * 32 * DD;
                if (xv0) acc += w10 * row[(size_t)xi * DD];
                if (xv1) acc += w11 * row[(size_t)(xi + 1) * DD];
            }
        }
    }
    out[(size_t)(n * LQQ + lq) * DD + h * DHH + dh] = acc;
}

// ---------------- final residual combine ----------------
__global__ void __launch_bounds__(256) combine_kernel(
    const float* __restrict__ src3, const float* __restrict__ gamma1, const float* __restrict__ gamma2,
    const float* __restrict__ attn, const float* __restrict__ attn2, float* __restrict__ out)
{
    int idx = blockIdx.x * blockDim.x + threadIdx.x;
    int d = idx & (DD - 1);
    out[idx] = src3[idx] + gamma1[d] * (attn[idx] + gamma2[d] * attn2[idx]);
}

// ---------------- host launcher ----------------
extern "C" void kernel_launch(void* const* d_in, const int* in_sizes, int n_in,
                              void* d_out, int out_size)
{
    const float* src0 = (const float*)d_in[0];
    const float* src1 = (const float*)d_in[1];
    const float* src2 = (const float*)d_in[2];
    const float* src3 = (const float*)d_in[3];
    const float* qn_g = (const float*)d_in[4];
    const float* qn_b = (const float*)d_in[5];
    const float* fn_g = (const float*)d_in[6];
    const float* fn_b = (const float*)d_in[7];
    const float* n1_g = (const float*)d_in[8];
    const float* n1_b = (const float*)d_in[9];
    const float* gamma1 = (const float*)d_in[10];
    const float* gamma2 = (const float*)d_in[11];
    const float* ca_vw = (const float*)d_in[12];
    const float* ca_vb = (const float*)d_in[13];
    const float* ca_ow = (const float*)d_in[14];
    const float* ca_ob = (const float*)d_in[15];
    const float* ca_aw = (const float*)d_in[16];
    const float* ca_ab = (const float*)d_in[17];
    const float* ca_pw = (const float*)d_in[18];
    const float* ca_pb = (const float*)d_in[19];
    const float* sa_vw = (const float*)d_in[20];
    const float* sa_vb = (const float*)d_in[21];
    const float* sa_ow = (const float*)d_in[22];
    const float* sa_ob = (const float*)d_in[23];
    const float* sa_aw = (const float*)d_in[24];
    const float* sa_ab = (const float*)d_in[25];
    const float* sa_pw = (const float*)d_in[26];
    const float* sa_pb = (const float*)d_in[27];
    float* out = (float*)d_out;

    float *qn, *fn, *val, *off, *attw, *samp, *attn, *attn1;
    float *val2, *off2, *attw2, *samp2, *attn2;
    cudaGetSymbolAddress((void**)&qn,    g_qn);
    cudaGetSymbolAddress((void**)&fn,    g_fn);
    cudaGetSymbolAddress((void**)&val,   g_val);
    cudaGetSymbolAddress((void**)&off,   g_off);
    cudaGetSymbolAddress((void**)&attw,  g_attw);
    cudaGetSymbolAddress((void**)&samp,  g_samp);
    cudaGetSymbolAddress((void**)&attn,  g_attn);
    cudaGetSymbolAddress((void**)&attn1, g_attn1);
    cudaGetSymbolAddress((void**)&val2,  g_val2);
    cudaGetSymbolAddress((void**)&off2,  g_off2);
    cudaGetSymbolAddress((void**)&attw2, g_attw2);
    cudaGetSymbolAddress((void**)&samp2, g_samp2);
    cudaGetSymbolAddress((void**)&attn2, g_attn2);

    const int ROWS_Q = BB * LQQ;        // 4096
    const int ROWS_F = BB * 4 * LQQ;    // 16384

    // 1) layernorm(query=src3) -> qn ; layernorm of each src into concatenated fn
    layernorm_kernel<<<ROWS_Q, 256>>>(src3, qn_g, qn_b, qn, LQQ, LQQ, 0);
    layernorm_kernel<<<ROWS_Q, 256>>>(src0, fn_g, fn_b, fn, LQQ, 4 * LQQ, 0 * LQQ);
    layernorm_kernel<<<ROWS_Q, 256>>>(src1, fn_g, fn_b, fn, LQQ, 4 * LQQ, 1 * LQQ);
    layernorm_kernel<<<ROWS_Q, 256>>>(src2, fn_g, fn_b, fn, LQQ, 4 * LQQ, 2 * LQQ);
    layernorm_kernel<<<ROWS_Q, 256>>>(src3, fn_g, fn_b, fn, LQQ, 4 * LQQ, 3 * LQQ);

    // 2) CA projections
    gemm_bias_kernel<<<dim3(DD / 64, ROWS_F / 64), 256>>>(fn, ca_vw, ca_vb, val, ROWS_F, DD, DD);
    gemm_bias_kernel<<<dim3(512 / 64, ROWS_Q / 64), 256>>>(qn, ca_ow, ca_ob, off, ROWS_Q, 512, DD);
    gemm_bias_kernel<<<dim3(256 / 64, ROWS_Q / 64), 256>>>(qn, ca_aw, ca_ab, attw, ROWS_Q, 256, DD);
    softmax_kernel<16><<<(BB * LQQ * NHH + 255) / 256, 256>>>(attw, BB * LQQ * NHH);

    // 3) CA sampling + output proj
    sample_kernel<4><<<dim3(NHH, LQQ, BB), DHH>>>(val, off, attw, samp);
    gemm_bias_kernel<<<dim3(DD / 64, ROWS_Q / 64), 256>>>(samp, ca_pw, ca_pb, attn, ROWS_Q, DD, DD);

    // 4) layernorm -> attn1
    layernorm_kernel<<<ROWS_Q, 256>>>(attn, n1_g, n1_b, attn1, LQQ, LQQ, 0);

    // 5) SA projections
    gemm_bias_kernel<<<dim3(DD / 64, ROWS_Q / 64), 256>>>(attn1, sa_vw, sa_vb, val2, ROWS_Q, DD, DD);
    gemm_bias_kernel<<<dim3(128 / 64, ROWS_Q / 64), 256>>>(attn1, sa_ow, sa_ob, off2, ROWS_Q, 128, DD);
    gemm_bias_kernel<<<dim3(64 / 64, ROWS_Q / 64), 256>>>(attn1, sa_aw, sa_ab, attw2, ROWS_Q, 64, DD);
    softmax_kernel<4><<<(BB * LQQ * NHH + 255) / 256, 256>>>(attw2, BB * LQQ * NHH);

    // 6) SA sampling + output proj
    sample_kernel<1><<<dim3(NHH, LQQ, BB), DHH>>>(val2, off2, attw2, samp2);
    gemm_bias_kernel<<<dim3(DD / 64, ROWS_Q / 64), 256>>>(samp2, sa_pw, sa_pb, attn2, ROWS_Q, DD, DD);

    // 7) residual combine
    combine_kernel<<<(BB * LQQ * DD) / 256, 256>>>(src3, gamma1, gamma2, attn, attn2, out);
}

// round 3
// speedup vs baseline: 2.8434x; 2.8434x over previous
#include <cuda_runtime.h>
#include <math.h>
#include <stdint.h>

// Problem constants
#define BB 4
#define DD 1024
#define NHH 16
#define DHH 64
#define LQQ 1024
#define NPP 4

// ---------------- scratch (device globals; no allocation allowed) ----------------
__device__ float g_qn   [BB * LQQ * DD];
__device__ float g_fn   [BB * 4 * LQQ * DD];
__device__ float g_val  [BB * 4 * LQQ * DD];
__device__ float g_off  [BB * LQQ * 512];
__device__ float g_attw [BB * LQQ * 256];
__device__ float g_samp [BB * LQQ * DD];
__device__ float g_attn [BB * LQQ * DD];
__device__ float g_attn1[BB * LQQ * DD];
__device__ float g_val2 [BB * LQQ * DD];
__device__ float g_off2 [BB * LQQ * 128];
__device__ float g_attw2[BB * LQQ * 64];
__device__ float g_samp2[BB * LQQ * DD];
__device__ float g_attn2[BB * LQQ * DD];

// ---------------- helpers ----------------
__device__ __forceinline__ uint32_t f2tf32(float f) {
    uint32_t r;
    asm("cvt.rna.tf32.f32 %0, %1;" : "=r"(r) : "f"(f));
    return r;
}

__device__ __forceinline__ void mma_tf32(float4& d, const uint4& a, const uint2& b) {
    asm("mma.sync.aligned.m16n8k8.row.col.f32.tf32.tf32.f32 "
        "{%0,%1,%2,%3}, {%4,%5,%6,%7}, {%8,%9}, {%0,%1,%2,%3};"
        : "+f"(d.x), "+f"(d.y), "+f"(d.z), "+f"(d.w)
        : "r"(a.x), "r"(a.y), "r"(a.z), "r"(a.w), "r"(b.x), "r"(b.y));
}

// ---------------- tensor-core GEMM: C[M,N] = A[M,K] @ W[N,K]^T + bias ----------------
// Block tile 128 x NT, BK=32, 256 threads = 8 warps (2 x 4 in m x n).
// SMEM tiles are stored pre-permuted in mma fragment order:
//   sA[((ks*8 + mtile)*32 + (g*4 + (t^ks)))*4 + (hi + 2*khi)]
//     = tf32(A[m0 + mtile*16 + g + 8*hi][k0 + ks*8 + t + 4*khi])
//   sB[((ks*NTI + ntile)*32 + (g*4 + (t^ks)))*2 + j2]
//     = tf32(W[n0 + ntile*8 + g][k0 + ks*8 + t + 4*j2])
// so the hot loop reads one LDS.128 per A-frag and one LDS.64 per B-frag.
template<int NT>
__global__ void __launch_bounds__(256) mma_gemm_kernel(
    const float* __restrict__ A, const float* __restrict__ W,
    const float* __restrict__ bias, float* __restrict__ C,
    int M, int N, int K)
{
    constexpr int NTI   = NT / 8;    // 8-wide n tiles in block
    constexpr int NFRAG = NT / 32;   // n frags per warp (4 warps across n)
    constexpr int B_F4  = NT / 32;   // B float4 loads per thread

    __shared__ float sA[4096];
    __shared__ float sB[256 * NTI];

    const int tid = threadIdx.x;
    const int lane = tid & 31;
    const int w = tid >> 5;
    const int warp_m = w >> 2;       // 0..1 (64 rows each)
    const int warp_n = w & 3;        // 0..3
    const int m0 = blockIdx.y * 128;
    const int n0 = blockIdx.x * NT;

    float4 acc[4][NFRAG];
    #pragma unroll
    for (int i = 0; i < 4; i++)
        #pragma unroll
        for (int j = 0; j < NFRAG; j++)
            acc[i][j] = make_float4(0.f, 0.f, 0.f, 0.f);

    float4 ra[4], rb[B_F4];
    #pragma unroll
    for (int i = 0; i < 4; i++) {
        int e = i * 256 + tid, row = e >> 3, q = e & 7;
        ra[i] = *(const float4*)(A + (size_t)(m0 + row) * K + q * 4);
    }
    #pragma unroll
    for (int i = 0; i < B_F4; i++) {
        int e = i * 256 + tid, row = e >> 3, q = e & 7;
        rb[i] = *(const float4*)(W + (size_t)(n0 + row) * K + q * 4);
    }

    const int NCH = K >> 5;
    for (int it = 0; it < NCH; it++) {
        __syncthreads();   // previous iteration's mma reads are done

        // store A tile (cvt to tf32, fragment-order permuted)
        #pragma unroll
        for (int i = 0; i < 4; i++) {
            int e = i * 256 + tid, row = e >> 3, q = e & 7;
            int ks = q >> 1, khi = q & 1;
            int mt = row >> 4, rr = row & 15, g = rr & 7, hi = rr >> 3;
            int base = (ks * 8 + mt) * 32 + g * 4;
            int j = hi + 2 * khi;
            sA[(base + (0 ^ ks)) * 4 + j] = __uint_as_float(f2tf32(ra[i].x));
            sA[(base + (1 ^ ks)) * 4 + j] = __uint_as_float(f2tf32(ra[i].y));
            sA[(base + (2 ^ ks)) * 4 + j] = __uint_as_float(f2tf32(ra[i].z));
            sA[(base + (3 ^ ks)) * 4 + j] = __uint_as_float(f2tf32(ra[i].w));
        }
        // store B tile
        #pragma unroll
        for (int i = 0; i < B_F4; i++) {
            int e = i * 256 + tid, row = e >> 3, q = e & 7;
            int ks = q >> 1, j2 = q & 1;
            int nt = row >> 3, g = row & 7;
            int base = (ks * NTI + nt) * 32 + g * 4;
            sB[(base + (0 ^ ks)) * 2 + j2] = __uint_as_float(f2tf32(rb[i].x));
            sB[(base + (1 ^ ks)) * 2 + j2] = __uint_as_float(f2tf32(rb[i].y));
            sB[(base + (2 ^ ks)) * 2 + j2] = __uint_as_float(f2tf32(rb[i].z));
            sB[(base + (3 ^ ks)) * 2 + j2] = __uint_as_float(f2tf32(rb[i].w));
        }
        __syncthreads();

        // prefetch next chunk while mma runs
        if (it + 1 < NCH) {
            const int k0 = (it + 1) * 32;
            #pragma unroll
            for (int i = 0; i < 4; i++) {
                int e = i * 256 + tid, row = e >> 3, q = e & 7;
                ra[i] = *(const float4*)(A + (size_t)(m0 + row) * K + k0 + q * 4);
            }
            #pragma unroll
            for (int i = 0; i < B_F4; i++) {
                int e = i * 256 + tid, row = e >> 3, q = e & 7;
                rb[i] = *(const float4*)(W + (size_t)(n0 + row) * K + k0 + q * 4);
            }
        }

        // mma over 4 k-steps
        #pragma unroll
        for (int ks = 0; ks < 4; ks++) {
            const int lx = lane ^ ks;   // ks<=3: only flips t bits
            uint4 av[4];
            uint2 bv[NFRAG];
            #pragma unroll
            for (int mf = 0; mf < 4; mf++)
                av[mf] = *(const uint4*)(sA + ((size_t)(ks * 8 + warp_m * 4 + mf) * 32 + lx) * 4);
            #pragma unroll
            for (int nf = 0; nf < NFRAG; nf++)
                bv[nf] = *(const uint2*)(sB + ((size_t)(ks * NTI + warp_n * NFRAG + nf) * 32 + lx) * 2);
            #pragma unroll
            for (int mf = 0; mf < 4; mf++)
                #pragma unroll
                for (int nf = 0; nf < NFRAG; nf++)
                    mma_tf32(acc[mf][nf], av[mf], bv[nf]);
        }
    }

    // epilogue: c0=(g,2t) c1=(g,2t+1) c2=(g+8,2t) c3=(g+8,2t+1)
    const int g = lane >> 2, t = lane & 3;
    #pragma unroll
    for (int mf = 0; mf < 4; mf++) {
        int mr = m0 + warp_m * 64 + mf * 16 + g;
        #pragma unroll
        for (int nf = 0; nf < NFRAG; nf++) {
            int nc = n0 + (warp_n * NFRAG + nf) * 8 + 2 * t;
            float b0 = __ldg(bias + nc), b1 = __ldg(bias + nc + 1);
            float2 o01 = make_float2(acc[mf][nf].x + b0, acc[mf][nf].y + b1);
            float2 o23 = make_float2(acc[mf][nf].z + b0, acc[mf][nf].w + b1);
            *(float2*)(C + (size_t)mr * N + nc) = o01;
            *(float2*)(C + (size_t)(mr + 8) * N + nc) = o23;
        }
    }
}

// ---------------- layernorm: one block (256 thr) per row of 1024 ----------------
__global__ void __launch_bounds__(256) layernorm_kernel(
    const float* __restrict__ in, const float* __restrict__ g, const float* __restrict__ b,
    float* __restrict__ out)
{
    int r = blockIdx.x;
    const float* x = in + (size_t)r * DD;
    float* y = out + (size_t)r * DD;
    int t = threadIdx.x;

    float4 v = ((const float4*)x)[t];
    float s  = v.x + v.y + v.z + v.w;
    float ss = v.x*v.x + v.y*v.y + v.z*v.z + v.w*v.w;
    #pragma unroll
    for (int o = 16; o > 0; o >>= 1) {
        s  += __shfl_xor_sync(0xffffffffu, s,  o);
        ss += __shfl_xor_sync(0xffffffffu, ss, o);
    }
    __shared__ float sh_s[8], sh_ss[8];
    int wid = t >> 5, lane = t & 31;
    if (lane == 0) { sh_s[wid] = s; sh_ss[wid] = ss; }
    __syncthreads();
    s = 0.f; ss = 0.f;
    #pragma unroll
    for (int i = 0; i < 8; i++) { s += sh_s[i]; ss += sh_ss[i]; }
    float mean = s * (1.0f / DD);
    float var  = ss * (1.0f / DD) - mean * mean;
    float inv  = rsqrtf(var + 1e-6f);

    float4 gg = ((const float4*)g)[t];
    float4 bb2 = ((const float4*)b)[t];
    float4 o4;
    o4.x = (v.x - mean) * inv * gg.x + bb2.x;
    o4.y = (v.y - mean) * inv * gg.y + bb2.y;
    o4.z = (v.z - mean) * inv * gg.z + bb2.z;
    o4.w = (v.w - mean) * inv * gg.w + bb2.w;
    ((float4*)y)[t] = o4;
}

// 4-source batched layernorm into concatenated feat buffer (B, 4*LQ, D)
__global__ void __launch_bounds__(256) layernorm4_kernel(
    const float* __restrict__ s0, const float* __restrict__ s1,
    const float* __restrict__ s2, const float* __restrict__ s3,
    const float* __restrict__ g, const float* __restrict__ b, float* __restrict__ out)
{
    int r = blockIdx.x;
    int level = r >> 12;
    int rr = r & 4095;
    const float* src = (level == 0) ? s0 : (level == 1) ? s1 : (level == 2) ? s2 : s3;
    const float* x = src + (size_t)rr * DD;
    int n = rr >> 10, q = rr & 1023;
    float* y = out + ((size_t)n * (4 * LQQ) + level * LQQ + q) * DD;
    int t = threadIdx.x;

    float4 v = ((const float4*)x)[t];
    float s  = v.x + v.y + v.z + v.w;
    float ss = v.x*v.x + v.y*v.y + v.z*v.z + v.w*v.w;
    #pragma unroll
    for (int o = 16; o > 0; o >>= 1) {
        s  += __shfl_xor_sync(0xffffffffu, s,  o);
        ss += __shfl_xor_sync(0xffffffffu, ss, o);
    }
    __shared__ float sh_s[8], sh_ss[8];
    int wid = t >> 5, lane = t & 31;
    if (lane == 0) { sh_s[wid] = s; sh_ss[wid] = ss; }
    __syncthreads();
    s = 0.f; ss = 0.f;
    #pragma unroll
    for (int i = 0; i < 8; i++) { s += sh_s[i]; ss += sh_ss[i]; }
    float mean = s * (1.0f / DD);
    float var  = ss * (1.0f / DD) - mean * mean;
    float inv  = rsqrtf(var + 1e-6f);

    float4 gg = ((const float4*)g)[t];
    float4 bb2 = ((const float4*)b)[t];
    float4 o4;
    o4.x = (v.x - mean) * inv * gg.x + bb2.x;
    o4.y = (v.y - mean) * inv * gg.y + bb2.y;
    o4.z = (v.z - mean) * inv * gg.z + bb2.z;
    o4.w = (v.w - mean) * inv * gg.w + bb2.w;
    ((float4*)y)[t] = o4;
}

// ---------------- softmax over P contiguous values ----------------
template<int P>
__global__ void softmax_kernel(float* __restrict__ w, int ngroups)
{
    int gid = blockIdx.x * blockDim.x + threadIdx.x;
    if (gid >= ngroups) return;
    float* p = w + (size_t)gid * P;
    float mx = p[0];
    #pragma unroll
    for (int i = 1; i < P; i++) mx = fmaxf(mx, p[i]);
    float s = 0.f;
    float e[P];
    #pragma unroll
    for (int i = 0; i < P; i++) { e[i] = __expf(p[i] - mx); s += e[i]; }
    float inv = 1.0f / s;
    #pragma unroll
    for (int i = 0; i < P; i++) p[i] = e[i] * inv;
}

// ---------------- deformable sampling ----------------
template<int NL>
__global__ void __launch_bounds__(64) sample_kernel(
    const float* __restrict__ val,
    const float* __restrict__ off,
    const float* __restrict__ attw,
    float* __restrict__ out)
{
    const int h  = blockIdx.x;
    const int lq = blockIdx.y;
    const int n  = blockIdx.z;
    const int dh = threadIdx.x;

    const float refx = ((lq & 31) + 0.5f) * 0.03125f;
    const float refy = ((lq >> 5) + 0.5f) * 0.03125f;

    const float* op = off  + (size_t)(n * LQQ + lq) * (NL * 128) + h * (NL * 8);
    const float* wp = attw + (size_t)(n * LQQ + lq) * (NL * 64)  + h * (NL * 4);
    const float* vb = val  + (size_t)n * (NL * LQQ) * DD + h * DHH + dh;

    float acc = 0.f;
    #pragma unroll
    for (int l = 0; l < NL; l++) {
        const float* vl = vb + (size_t)l * LQQ * DD;
        #pragma unroll
        for (int p = 0; p < NPP; p++) {
            float ox = op[l * 8 + p * 2 + 0];
            float oy = op[l * 8 + p * 2 + 1];
            float x = (refx + ox * 0.03125f) * 32.f - 0.5f;
            float y = (refy + oy * 0.03125f) * 32.f - 0.5f;
            float x0f = floorf(x), y0f = floorf(y);
            int xi = (int)x0f, yi = (int)y0f;
            float fx = x - x0f, fy = y - y0f;
            float w = wp[l * 4 + p];
            float w00 = (1.f - fy) * (1.f - fx) * w;
            float w01 = (1.f - fy) * fx * w;
            float w10 = fy * (1.f - fx) * w;
            float w11 = fy * fx * w;
            bool xv0 = (xi >= 0) && (xi < 32);
            bool xv1 = (xi + 1 >= 0) && (xi + 1 < 32);
            if (yi >= 0 && yi < 32) {
                const float* row = vl + (size_t)yi * 32 * DD;
                if (xv0) acc += w00 * row[(size_t)xi * DD];
                if (xv1) acc += w01 * row[(size_t)(xi + 1) * DD];
            }
            if (yi + 1 >= 0 && yi + 1 < 32) {
                const float* row = vl + (size_t)(yi + 1) * 32 * DD;
                if (xv0) acc += w10 * row[(size_t)xi * DD];
                if (xv1) acc += w11 * row[(size_t)(xi + 1) * DD];
            }
        }
    }
    out[(size_t)(n * LQQ + lq) * DD + h * DHH + dh] = acc;
}

// ---------------- final residual combine ----------------
__global__ void __launch_bounds__(256) combine_kernel(
    const float* __restrict__ src3, const float* __restrict__ gamma1, const float* __restrict__ gamma2,
    const float* __restrict__ attn, const float* __restrict__ attn2, float* __restrict__ out)
{
    int idx = blockIdx.x * blockDim.x + threadIdx.x;
    int d = idx & (DD - 1);
    out[idx] = src3[idx] + gamma1[d] * (attn[idx] + gamma2[d] * attn2[idx]);
}

// ---------------- host launcher ----------------
extern "C" void kernel_launch(void* const* d_in, const int* in_sizes, int n_in,
                              void* d_out, int out_size)
{
    const float* src0 = (const float*)d_in[0];
    const float* src1 = (const float*)d_in[1];
    const float* src2 = (const float*)d_in[2];
    const float* src3 = (const float*)d_in[3];
    const float* qn_g = (const float*)d_in[4];
    const float* qn_b = (const float*)d_in[5];
    const float* fn_g = (const float*)d_in[6];
    const float* fn_b = (const float*)d_in[7];
    const float* n1_g = (const float*)d_in[8];
    const float* n1_b = (const float*)d_in[9];
    const float* gamma1 = (const float*)d_in[10];
    const float* gamma2 = (const float*)d_in[11];
    const float* ca_vw = (const float*)d_in[12];
    const float* ca_vb = (const float*)d_in[13];
    const float* ca_ow = (const float*)d_in[14];
    const float* ca_ob = (const float*)d_in[15];
    const float* ca_aw = (const float*)d_in[16];
    const float* ca_ab = (const float*)d_in[17];
    const float* ca_pw = (const float*)d_in[18];
    const float* ca_pb = (const float*)d_in[19];
    const float* sa_vw = (const float*)d_in[20];
    const float* sa_vb = (const float*)d_in[21];
    const float* sa_ow = (const float*)d_in[22];
    const float* sa_ob = (const float*)d_in[23];
    const float* sa_aw = (const float*)d_in[24];
    const float* sa_ab = (const float*)d_in[25];
    const float* sa_pw = (const float*)d_in[26];
    const float* sa_pb = (const float*)d_in[27];
    float* out = (float*)d_out;

    float *qn, *fn, *val, *off, *attw, *samp, *attn, *attn1;
    float *val2, *off2, *attw2, *samp2, *attn2;
    cudaGetSymbolAddress((void**)&qn,    g_qn);
    cudaGetSymbolAddress((void**)&fn,    g_fn);
    cudaGetSymbolAddress((void**)&val,   g_val);
    cudaGetSymbolAddress((void**)&off,   g_off);
    cudaGetSymbolAddress((void**)&attw,  g_attw);
    cudaGetSymbolAddress((void**)&samp,  g_samp);
    cudaGetSymbolAddress((void**)&attn,  g_attn);
    cudaGetSymbolAddress((void**)&attn1, g_attn1);
    cudaGetSymbolAddress((void**)&val2,  g_val2);
    cudaGetSymbolAddress((void**)&off2,  g_off2);
    cudaGetSymbolAddress((void**)&attw2, g_attw2);
    cudaGetSymbolAddress((void**)&samp2, g_samp2);
    cudaGetSymbolAddress((void**)&attn2, g_attn2);

    const int ROWS_Q = BB * LQQ;        // 4096
    const int ROWS_F = BB * 4 * LQQ;    // 16384

    // 1) layernorms
    layernorm_kernel<<<ROWS_Q, 256>>>(src3, qn_g, qn_b, qn);
    layernorm4_kernel<<<4 * ROWS_Q, 256>>>(src0, src1, src2, src3, fn_g, fn_b, fn);

    // 2) CA projections (tensor core tf32)
    mma_gemm_kernel<128><<<dim3(8, 128), 256>>>(fn, ca_vw, ca_vb, val, ROWS_F, DD, DD);
    mma_gemm_kernel<128><<<dim3(4, 32), 256>>>(qn, ca_ow, ca_ob, off, ROWS_Q, 512, DD);
    mma_gemm_kernel<128><<<dim3(2, 32), 256>>>(qn, ca_aw, ca_ab, attw, ROWS_Q, 256, DD);
    softmax_kernel<16><<<(BB * LQQ * NHH + 255) / 256, 256>>>(attw, BB * LQQ * NHH);

    // 3) CA sampling + output proj
    sample_kernel<4><<<dim3(NHH, LQQ, BB), DHH>>>(val, off, attw, samp);
    mma_gemm_kernel<128><<<dim3(8, 32), 256>>>(samp, ca_pw, ca_pb, attn, ROWS_Q, DD, DD);

    // 4) layernorm -> attn1
    layernorm_kernel<<<ROWS_Q, 256>>>(attn, n1_g, n1_b, attn1);

    // 5) SA projections
    mma_gemm_kernel<128><<<dim3(8, 32), 256>>>(attn1, sa_vw, sa_vb, val2, ROWS_Q, DD, DD);
    mma_gemm_kernel<128><<<dim3(1, 32), 256>>>(attn1, sa_ow, sa_ob, off2, ROWS_Q, 128, DD);
    mma_gemm_kernel<64><<<dim3(1, 32), 256>>>(attn1, sa_aw, sa_ab, attw2, ROWS_Q, 64, DD);
    softmax_kernel<4><<<(BB * LQQ * NHH + 255) / 256, 256>>>(attw2, BB * LQQ * NHH);

    // 6) SA sampling + output proj
    sample_kernel<1><<<dim3(NHH, LQQ, BB), DHH>>>(val2, off2, attw2, samp2);
    mma_gemm_kernel<128><<<dim3(8, 32), 256>>>(samp2, sa_pw, sa_pb, attn2, ROWS_Q, DD, DD);

    // 7) residual combine
    combine_kernel<<<(BB * LQQ * DD) / 256, 256>>>(src3, gamma1, gamma2, attn, attn2, out);
}

// round 4
// speedup vs baseline: 4.6968x; 1.6518x over previous
#include <cuda_runtime.h>
#include <cuda_bf16.h>
#include <math.h>
#include <stdint.h>

// Problem constants
#define BB 4
#define DD 1024
#define NHH 16
#define DHH 64
#define LQQ 1024
#define NPP 4

typedef __nv_bfloat16 bf16;
typedef __nv_bfloat162 bf162;

// ---------------- scratch (device globals; no allocation allowed) ----------------
__device__ bf16  g_qn_bf   [BB * LQQ * DD];
__device__ bf16  g_fn_bf   [BB * 4 * LQQ * DD];
__device__ bf16  g_wbf     [5177344];               // all 8 weight matrices in bf16
__device__ bf16  g_val_bf  [BB * 4 * LQQ * DD];
__device__ float g_off     [BB * LQQ * 512];
__device__ float g_attw    [BB * LQQ * 256];
__device__ bf16  g_samp_bf [BB * LQQ * DD];
__device__ float g_attn    [BB * LQQ * DD];
__device__ bf16  g_attn1_bf[BB * LQQ * DD];
__device__ bf16  g_val2_bf [BB * LQQ * DD];
__device__ float g_off2    [BB * LQQ * 128];
__device__ float g_attw2   [BB * LQQ * 64];
__device__ bf16  g_samp2_bf[BB * LQQ * DD];
__device__ float g_attn2   [BB * LQQ * DD];

// weight offsets within g_wbf
#define W_CAVW 0
#define W_CAOW 1048576
#define W_CAAW 1572864
#define W_CAPW 1835008
#define W_SAVW 2883584
#define W_SAOW 3932160
#define W_SAPW 4128768   // note: sa_aw goes after sa_ow
#define W_SAAW 4063232

// ---------------- helpers ----------------
__device__ __forceinline__ void mma_bf16(float4& d, const uint32_t* a, const uint32_t* b) {
    asm("mma.sync.aligned.m16n8k16.row.col.f32.bf16.bf16.f32 "
        "{%0,%1,%2,%3}, {%4,%5,%6,%7}, {%8,%9}, {%0,%1,%2,%3};"
        : "+f"(d.x), "+f"(d.y), "+f"(d.z), "+f"(d.w)
        : "r"(a[0]), "r"(a[1]), "r"(a[2]), "r"(a[3]), "r"(b[0]), "r"(b[1]));
}

__device__ __forceinline__ void cp_async16(uint32_t dst, const void* src) {
    asm volatile("cp.async.cg.shared.global [%0], [%1], 16;" :: "r"(dst), "l"(src) : "memory");
}

// ---------------- bf16 tensor-core GEMM: C[M,N] = A[M,K] @ W[N,K]^T + bias ----------------
// Block tile 128 x NT, BK=32, 256 threads = 8 warps (2 x 4 m x n), 4-stage cp.async pipe.
// SMEM tile rows: 32 bf16 = 64B = 4 chunks of 16B; chunk swizzle: c' = c ^ ((row>>1)&3).
template<int NT, bool BF16_OUT>
__global__ void __launch_bounds__(256, 2) bf16_gemm_kernel(
    const bf16* __restrict__ A, const bf16* __restrict__ W,
    const float* __restrict__ bias, void* __restrict__ Cv,
    int M, int N, int K)
{
    constexpr int NFRAG = NT / 32;       // n frags per warp
    constexpr int B_CH  = NT / 64;       // B cp.async chunks per thread
    constexpr int ASZ   = 128 * 64;      // 8192 B
    constexpr int BSZ   = NT * 64;
    constexpr int STG   = ASZ + BSZ;
    constexpr int S     = 4;

    extern __shared__ __align__(16) char dsm[];

    const int tid = threadIdx.x;
    const int lane = tid & 31;
    const int w = tid >> 5;
    const int warp_m = w >> 2;
    const int warp_n = w & 3;
    const int g = lane >> 2, t = lane & 3;
    const int m0 = blockIdx.y * 128;
    const int n0 = blockIdx.x * NT;

    uint32_t smem_u32 = (uint32_t)__cvta_generic_to_shared(dsm);

    // cp.async thread assignment (fixed per thread)
    const int arow0 = tid >> 2, ac0 = tid & 3;           // A chunk 1 of 2
    const int arow1 = (tid + 256) >> 2, ac1 = tid & 3;   // A chunk 2 of 2 (rows 64..127)

    float4 acc[4][NFRAG];
    #pragma unroll
    for (int i = 0; i < 4; i++)
        #pragma unroll
        for (int j = 0; j < NFRAG; j++) acc[i][j] = make_float4(0.f,0.f,0.f,0.f);

    auto issue = [&](int stage, int k0) {
        uint32_t sa = smem_u32 + stage * STG;
        uint32_t sb = sa + ASZ;
        // A: 512 chunks, 2 per thread
        {
            int row = arow0, c = ac0;
            cp_async16(sa + row*64 + ((c ^ ((row>>1)&3))<<4),
                       A + (size_t)(m0+row)*K + k0 + c*8);
            row = arow1; c = ac1;
            cp_async16(sa + row*64 + ((c ^ ((row>>1)&3))<<4),
                       A + (size_t)(m0+row)*K + k0 + c*8);
        }
        // B: NT*4 chunks
        #pragma unroll
        for (int i = 0; i < B_CH; i++) {
            int e = tid + i*256, row = e>>2, c = e&3;
            cp_async16(sb + row*64 + ((c ^ ((row>>1)&3))<<4),
                       W + (size_t)(n0+row)*K + k0 + c*8);
        }
        asm volatile("cp.async.commit_group;" ::: "memory");
    };

    const int NCH = K >> 5;    // 32
    issue(0, 0); issue(1, 32); issue(2, 64);

    for (int it = 0; it < NCH; it++) {
        asm volatile("cp.async.wait_group 2;" ::: "memory");
        __syncthreads();
        if (it + S - 1 < NCH) issue((it + S - 1) & (S - 1), (it + S - 1) << 5);
        else asm volatile("cp.async.commit_group;" ::: "memory");

        const char* sa = dsm + (it & (S - 1)) * STG;
        const char* sb = sa + ASZ;

        #pragma unroll
        for (int ks = 0; ks < 2; ks++) {
            uint32_t a[4][4];
            uint32_t b[NFRAG][2];
            #pragma unroll
            for (int mf = 0; mf < 4; mf++) {
                int row = warp_m*64 + mf*16 + g;
                int ax = row*64 + (((ks*2) ^ ((row>>1)&3))<<4) + 4*t;
                a[mf][0] = *(const uint32_t*)(sa + ax);
                a[mf][1] = *(const uint32_t*)(sa + ax + 512);
                a[mf][2] = *(const uint32_t*)(sa + (ax ^ 16));
                a[mf][3] = *(const uint32_t*)(sa + ((ax + 512) ^ 16));
            }
            #pragma unroll
            for (int nf = 0; nf < NFRAG; nf++) {
                int row = warp_n*(NFRAG*8) + nf*8 + g;
                int bx = row*64 + (((ks*2) ^ ((row>>1)&3))<<4) + 4*t;
                b[nf][0] = *(const uint32_t*)(sb + bx);
                b[nf][1] = *(const uint32_t*)(sb + (bx ^ 16));
            }
            #pragma unroll
            for (int mf = 0; mf < 4; mf++)
                #pragma unroll
                for (int nf = 0; nf < NFRAG; nf++)
                    mma_bf16(acc[mf][nf], a[mf], b[nf]);
        }
    }

    // epilogue: c0=(g,2t) c1=(g,2t+1) c2=(g+8,2t) c3=(g+8,2t+1)
    #pragma unroll
    for (int mf = 0; mf < 4; mf++) {
        int mr = m0 + warp_m*64 + mf*16 + g;
        #pragma unroll
        for (int nf = 0; nf < NFRAG; nf++) {
            int nc = n0 + (warp_n*NFRAG + nf)*8 + 2*t;
            float b0 = __ldg(bias + nc), b1 = __ldg(bias + nc + 1);
            float ox = acc[mf][nf].x + b0, oy = acc[mf][nf].y + b1;
            float oz = acc[mf][nf].z + b0, ow = acc[mf][nf].w + b1;
            if (BF16_OUT) {
                bf16* C = (bf16*)Cv;
                *(bf162*)(C + (size_t)mr * N + nc)       = __floats2bfloat162_rn(ox, oy);
                *(bf162*)(C + (size_t)(mr + 8) * N + nc) = __floats2bfloat162_rn(oz, ow);
            } else {
                float* C = (float*)Cv;
                *(float2*)(C + (size_t)mr * N + nc)       = make_float2(ox, oy);
                *(float2*)(C + (size_t)(mr + 8) * N + nc) = make_float2(oz, ow);
            }
        }
    }
}

// ---------------- weight fp32 -> bf16 conversion (all 8 mats, one kernel) ----------------
__global__ void __launch_bounds__(256) wcvt_kernel(
    const float* w0, const float* w1, const float* w2, const float* w3,
    const float* w4, const float* w5, const float* w6, const float* w7)
{
    // block counts: 1024,512,256,1024,1024,128,64,1024 (x1024 elems each)
    int b = blockIdx.x;
    const float* src; bf16* dst;
    if      (b < 1024) { src = w0; dst = g_wbf + W_CAVW; }
    else if (b < 1536) { src = w1; dst = g_wbf + W_CAOW; b -= 1024; }
    else if (b < 1792) { src = w2; dst = g_wbf + W_CAAW; b -= 1536; }
    else if (b < 2816) { src = w3; dst = g_wbf + W_CAPW; b -= 1792; }
    else if (b < 3840) { src = w4; dst = g_wbf + W_SAVW; b -= 2816; }
    else if (b < 3968) { src = w5; dst = g_wbf + W_SAOW; b -= 3840; }
    else if (b < 4032) { src = w6; dst = g_wbf + W_SAAW; b -= 3968; }
    else               { src = w7; dst = g_wbf + W_SAPW; b -= 4032; }
    int idx = b * 1024 + threadIdx.x * 4;
    float4 v = *(const float4*)(src + idx);
    bf162 p0 = __floats2bfloat162_rn(v.x, v.y);
    bf162 p1 = __floats2bfloat162_rn(v.z, v.w);
    *(bf162*)(dst + idx) = p0;
    *(bf162*)(dst + idx + 2) = p1;
}

// ---------------- layernorm -> bf16 out, one block per row ----------------
__global__ void __launch_bounds__(256) layernorm_bf_kernel(
    const float* __restrict__ in, const float* __restrict__ g, const float* __restrict__ b,
    bf16* __restrict__ out)
{
    int r = blockIdx.x;
    const float* x = in + (size_t)r * DD;
    bf16* y = out + (size_t)r * DD;
    int t = threadIdx.x;

    float4 v = ((const float4*)x)[t];
    float s  = v.x + v.y + v.z + v.w;
    float ss = v.x*v.x + v.y*v.y + v.z*v.z + v.w*v.w;
    #pragma unroll
    for (int o = 16; o > 0; o >>= 1) {
        s  += __shfl_xor_sync(0xffffffffu, s,  o);
        ss += __shfl_xor_sync(0xffffffffu, ss, o);
    }
    __shared__ float sh_s[8], sh_ss[8];
    int wid = t >> 5, lane = t & 31;
    if (lane == 0) { sh_s[wid] = s; sh_ss[wid] = ss; }
    __syncthreads();
    s = 0.f; ss = 0.f;
    #pragma unroll
    for (int i = 0; i < 8; i++) { s += sh_s[i]; ss += sh_ss[i]; }
    float mean = s * (1.0f / DD);
    float var  = ss * (1.0f / DD) - mean * mean;
    float inv  = rsqrtf(var + 1e-6f);

    float4 gg = ((const float4*)g)[t];
    float4 bb2 = ((const float4*)b)[t];
    ((bf162*)y)[2*t]   = __floats2bfloat162_rn((v.x-mean)*inv*gg.x + bb2.x, (v.y-mean)*inv*gg.y + bb2.y);
    ((bf162*)y)[2*t+1] = __floats2bfloat162_rn((v.z-mean)*inv*gg.z + bb2.z, (v.w-mean)*inv*gg.w + bb2.w);
}

// 4-source batched layernorm -> concatenated bf16 feat (B, 4*LQ, D)
__global__ void __launch_bounds__(256) layernorm4_bf_kernel(
    const float* __restrict__ s0, const float* __restrict__ s1,
    const float* __restrict__ s2, const float* __restrict__ s3,
    const float* __restrict__ g, const float* __restrict__ b, bf16* __restrict__ out)
{
    int r = blockIdx.x;
    int level = r >> 12;
    int rr = r & 4095;
    const float* src = (level == 0) ? s0 : (level == 1) ? s1 : (level == 2) ? s2 : s3;
    const float* x = src + (size_t)rr * DD;
    int n = rr >> 10, q = rr & 1023;
    bf16* y = out + ((size_t)n * (4 * LQQ) + level * LQQ + q) * DD;
    int t = threadIdx.x;

    float4 v = ((const float4*)x)[t];
    float s  = v.x + v.y + v.z + v.w;
    float ss = v.x*v.x + v.y*v.y + v.z*v.z + v.w*v.w;
    #pragma unroll
    for (int o = 16; o > 0; o >>= 1) {
        s  += __shfl_xor_sync(0xffffffffu, s,  o);
        ss += __shfl_xor_sync(0xffffffffu, ss, o);
    }
    __shared__ float sh_s[8], sh_ss[8];
    int wid = t >> 5, lane = t & 31;
    if (lane == 0) { sh_s[wid] = s; sh_ss[wid] = ss; }
    __syncthreads();
    s = 0.f; ss = 0.f;
    #pragma unroll
    for (int i = 0; i < 8; i++) { s += sh_s[i]; ss += sh_ss[i]; }
    float mean = s * (1.0f / DD);
    float var  = ss * (1.0f / DD) - mean * mean;
    float inv  = rsqrtf(var + 1e-6f);

    float4 gg = ((const float4*)g)[t];
    float4 bb2 = ((const float4*)b)[t];
    ((bf162*)y)[2*t]   = __floats2bfloat162_rn((v.x-mean)*inv*gg.x + bb2.x, (v.y-mean)*inv*gg.y + bb2.y);
    ((bf162*)y)[2*t+1] = __floats2bfloat162_rn((v.z-mean)*inv*gg.z + bb2.z, (v.w-mean)*inv*gg.w + bb2.w);
}

// ---------------- softmax over P contiguous values ----------------
template<int P>
__global__ void softmax_kernel(float* __restrict__ w, int ngroups)
{
    int gid = blockIdx.x * blockDim.x + threadIdx.x;
    if (gid >= ngroups) return;
    float* p = w + (size_t)gid * P;
    float mx = p[0];
    #pragma unroll
    for (int i = 1; i < P; i++) mx = fmaxf(mx, p[i]);
    float s = 0.f;
    float e[P];
    #pragma unroll
    for (int i = 0; i < P; i++) { e[i] = __expf(p[i] - mx); s += e[i]; }
    float inv = 1.0f / s;
    #pragma unroll
    for (int i = 0; i < P; i++) p[i] = e[i] * inv;
}

// ---------------- deformable sampling (bf16 values, bf16 out) ----------------
template<int NL>
__global__ void __launch_bounds__(64) sample_kernel(
    const bf16* __restrict__ val,
    const float* __restrict__ off,
    const float* __restrict__ attw,
    bf16* __restrict__ out)
{
    const int h  = blockIdx.x;
    const int lq = blockIdx.y;
    const int n  = blockIdx.z;
    const int dh = threadIdx.x;

    const float refx = ((lq & 31) + 0.5f) * 0.03125f;
    const float refy = ((lq >> 5) + 0.5f) * 0.03125f;

    const float* op = off  + (size_t)(n * LQQ + lq) * (NL * 128) + h * (NL * 8);
    const float* wp = attw + (size_t)(n * LQQ + lq) * (NL * 64)  + h * (NL * 4);
    const bf16* vb = val + (size_t)n * (NL * LQQ) * DD + h * DHH + dh;

    float acc = 0.f;
    #pragma unroll
    for (int l = 0; l < NL; l++) {
        const bf16* vl = vb + (size_t)l * LQQ * DD;
        #pragma unroll
        for (int p = 0; p < NPP; p++) {
            float ox = op[l * 8 + p * 2 + 0];
            float oy = op[l * 8 + p * 2 + 1];
            float x = (refx + ox * 0.03125f) * 32.f - 0.5f;
            float y = (refy + oy * 0.03125f) * 32.f - 0.5f;
            float x0f = floorf(x), y0f = floorf(y);
            int xi = (int)x0f, yi = (int)y0f;
            float fx = x - x0f, fy = y - y0f;
            float w = wp[l * 4 + p];
            float w00 = (1.f - fy) * (1.f - fx) * w;
            float w01 = (1.f - fy) * fx * w;
            float w10 = fy * (1.f - fx) * w;
            float w11 = fy * fx * w;
            bool xv0 = (xi >= 0) && (xi < 32);
            bool xv1 = (xi + 1 >= 0) && (xi + 1 < 32);
            if (yi >= 0 && yi < 32) {
                const bf16* row = vl + (size_t)yi * 32 * DD;
                if (xv0) acc += w00 * __bfloat162float(__ldg(row + (size_t)xi * DD));
                if (xv1) acc += w01 * __bfloat162float(__ldg(row + (size_t)(xi + 1) * DD));
            }
            if (yi + 1 >= 0 && yi + 1 < 32) {
                const bf16* row = vl + (size_t)(yi + 1) * 32 * DD;
                if (xv0) acc += w10 * __bfloat162float(__ldg(row + (size_t)xi * DD));
                if (xv1) acc += w11 * __bfloat162float(__ldg(row + (size_t)(xi + 1) * DD));
            }
        }
    }
    out[(size_t)(n * LQQ + lq) * DD + h * DHH + dh] = __float2bfloat16(acc);
}

// ---------------- final residual combine ----------------
__global__ void __launch_bounds__(256) combine_kernel(
    const float* __restrict__ src3, const float* __restrict__ gamma1, const float* __restrict__ gamma2,
    const float* __restrict__ attn, const float* __restrict__ attn2, float* __restrict__ out)
{
    int idx = blockIdx.x * blockDim.x + threadIdx.x;
    int d = idx & (DD - 1);
    out[idx] = src3[idx] + gamma1[d] * (attn[idx] + gamma2[d] * attn2[idx]);
}

// ---------------- host launcher ----------------
extern "C" void kernel_launch(void* const* d_in, const int* in_sizes, int n_in,
                              void* d_out, int out_size)
{
    const float* src0 = (const float*)d_in[0];
    const float* src1 = (const float*)d_in[1];
    const float* src2 = (const float*)d_in[2];
    const float* src3 = (const float*)d_in[3];
    const float* qn_g = (const float*)d_in[4];
    const float* qn_b = (const float*)d_in[5];
    const float* fn_g = (const float*)d_in[6];
    const float* fn_b = (const float*)d_in[7];
    const float* n1_g = (const float*)d_in[8];
    const float* n1_b = (const float*)d_in[9];
    const float* gamma1 = (const float*)d_in[10];
    const float* gamma2 = (const float*)d_in[11];
    const float* ca_vw = (const float*)d_in[12];
    const float* ca_vb = (const float*)d_in[13];
    const float* ca_ow = (const float*)d_in[14];
    const float* ca_ob = (const float*)d_in[15];
    const float* ca_aw = (const float*)d_in[16];
    const float* ca_ab = (const float*)d_in[17];
    const float* ca_pw = (const float*)d_in[18];
    const float* ca_pb = (const float*)d_in[19];
    const float* sa_vw = (const float*)d_in[20];
    const float* sa_vb = (const float*)d_in[21];
    const float* sa_ow = (const float*)d_in[22];
    const float* sa_ob = (const float*)d_in[23];
    const float* sa_aw = (const float*)d_in[24];
    const float* sa_ab = (const float*)d_in[25];
    const float* sa_pw = (const float*)d_in[26];
    const float* sa_pb = (const float*)d_in[27];
    float* out = (float*)d_out;

    static bool attr_done = false;
    if (!attr_done) {
        cudaFuncSetAttribute(bf16_gemm_kernel<128,true>,  cudaFuncAttributeMaxDynamicSharedMemorySize, 65536);
        cudaFuncSetAttribute(bf16_gemm_kernel<128,false>, cudaFuncAttributeMaxDynamicSharedMemorySize, 65536);
        cudaFuncSetAttribute(bf16_gemm_kernel<64,false>,  cudaFuncAttributeMaxDynamicSharedMemorySize, 49152);
        attr_done = true;
    }

    bf16 *qn, *fn, *wb, *val, *samp, *attn1, *val2, *samp2;
    float *off, *attw, *attn, *off2, *attw2, *attn2;
    cudaGetSymbolAddress((void**)&qn,    g_qn_bf);
    cudaGetSymbolAddress((void**)&fn,    g_fn_bf);
    cudaGetSymbolAddress((void**)&wb,    g_wbf);
    cudaGetSymbolAddress((void**)&val,   g_val_bf);
    cudaGetSymbolAddress((void**)&off,   g_off);
    cudaGetSymbolAddress((void**)&attw,  g_attw);
    cudaGetSymbolAddress((void**)&samp,  g_samp_bf);
    cudaGetSymbolAddress((void**)&attn,  g_attn);
    cudaGetSymbolAddress((void**)&attn1, g_attn1_bf);
    cudaGetSymbolAddress((void**)&val2,  g_val2_bf);
    cudaGetSymbolAddress((void**)&off2,  g_off2);
    cudaGetSymbolAddress((void**)&attw2, g_attw2);
    cudaGetSymbolAddress((void**)&samp2, g_samp2_bf);
    cudaGetSymbolAddress((void**)&attn2, g_attn2);

    const int ROWS_Q = BB * LQQ;        // 4096
    const int ROWS_F = BB * 4 * LQQ;    // 16384

    // 0) weights -> bf16
    wcvt_kernel<<<5056, 256>>>(ca_vw, ca_ow, ca_aw, ca_pw, sa_vw, sa_ow, sa_aw, sa_pw);

    // 1) layernorms (bf16 out)
    layernorm_bf_kernel<<<ROWS_Q, 256>>>(src3, qn_g, qn_b, qn);
    layernorm4_bf_kernel<<<4 * ROWS_Q, 256>>>(src0, src1, src2, src3, fn_g, fn_b, fn);

    // 2) CA projections
    bf16_gemm_kernel<128,true ><<<dim3(8, 128), 256, 65536>>>(fn, wb + W_CAVW, ca_vb, val,  ROWS_F, DD,  DD);
    bf16_gemm_kernel<128,false><<<dim3(4, 32),  256, 65536>>>(qn, wb + W_CAOW, ca_ob, off,  ROWS_Q, 512, DD);
    bf16_gemm_kernel<128,false><<<dim3(2, 32),  256, 65536>>>(qn, wb + W_CAAW, ca_ab, attw, ROWS_Q, 256, DD);
    softmax_kernel<16><<<(BB * LQQ * NHH + 255) / 256, 256>>>(attw, BB * LQQ * NHH);

    // 3) CA sampling + output proj
    sample_kernel<4><<<dim3(NHH, LQQ, BB), DHH>>>(val, off, attw, samp);
    bf16_gemm_kernel<128,false><<<dim3(8, 32), 256, 65536>>>(samp, wb + W_CAPW, ca_pb, attn, ROWS_Q, DD, DD);

    // 4) layernorm -> attn1 (bf16)
    layernorm_bf_kernel<<<ROWS_Q, 256>>>(attn, n1_g, n1_b, attn1);

    // 5) SA projections
    bf16_gemm_kernel<128,true ><<<dim3(8, 32), 256, 65536>>>(attn1, wb + W_SAVW, sa_vb, val2,  ROWS_Q, DD,  DD);
    bf16_gemm_kernel<128,false><<<dim3(1, 32), 256, 65536>>>(attn1, wb + W_SAOW, sa_ob, off2,  ROWS_Q, 128, DD);
    bf16_gemm_kernel<64, false><<<dim3(1, 32), 256, 49152>>>(attn1, wb + W_SAAW, sa_ab, attw2, ROWS_Q, 64,  DD);
    softmax_kernel<4><<<(BB * LQQ * NHH + 255) / 256, 256>>>(attw2, BB * LQQ * NHH);

    // 6) SA sampling + output proj
    sample_kernel<1><<<dim3(NHH, LQQ, BB), DHH>>>(val2, off2, attw2, samp2);
    bf16_gemm_kernel<128,false><<<dim3(8, 32), 256, 65536>>>(samp2, wb + W_SAPW, sa_pb, attn2, ROWS_Q, DD, DD);

    // 7) residual combine
    combine_kernel<<<(BB * LQQ * DD) / 256, 256>>>(src3, gamma1, gamma2, attn, attn2, out);
}